// round 12
// baseline (speedup 1.0000x reference)
#include <cuda_runtime.h>
#include <cuda_bf16.h>
#include <cstdint>
#include <math.h>

// Problem constants
#define B_   2
#define S_   2048
#define H_   4096
#define NH_  32
#define NKV_ 2
#define HD_  128
#define ROT_ 64
#define QKV_N 4608            // (NH + 2*NKV) * HD
#define TOKS (B_ * S_)        // 4096

// Scratch (device globals; no allocation allowed)
__device__ float g_qkv[(size_t)TOKS * QKV_N];   // ~75.5 MB
__device__ float g_attn[(size_t)TOKS * H_];     // ~67 MB

__device__ __forceinline__ float to_tf32(float x) {
    float y;
    asm("cvt.rna.tf32.f32 %0, %1;" : "=f"(y) : "f"(x));
    return y;
}

__device__ __forceinline__ void mma_tf32(float* d,
                                         const uint32_t* a,
                                         const uint32_t* b) {
    asm volatile(
        "mma.sync.aligned.m16n8k8.row.col.f32.tf32.tf32.f32 "
        "{%0,%1,%2,%3}, {%4,%5,%6,%7}, {%8,%9}, {%0,%1,%2,%3};\n"
        : "+f"(d[0]), "+f"(d[1]), "+f"(d[2]), "+f"(d[3])
        : "r"(a[0]), "r"(a[1]), "r"(a[2]), "r"(a[3]),
          "r"(b[0]), "r"(b[1]));
}

// ---------------------------------------------------------------------------
// TF32 tensor-core GEMM, double-buffered smem, ONE __syncthreads per stage.
// C[M,N] = A[M,K] @ B[K,N] (+bias). 128x128x32 CTA tile, 8 warps, 64x32 warp.
// DYNAMIC smem (71680 B):
//   As[2][128][36]  rows are 32 k-floats + pad4  (A-frag reads 4g+t, CF)
//   Bs[2][32][136]  rows are 128 n-floats + pad8 (B-frag reads 8t+8j+g, CF)
// (R10/R11 bug: B_PAD=40 < 128-wide row -> OOB smem writes. Row width of Bs
//  is the N dimension, NOT the K dimension. Restored to 136.)
// Occupancy: 124 regs -> 2 CTAs/SM; 2 x 71680 B = 143 KB < 228 KB/SM. OK.
// Pipeline: STS(buf s) ; sync ; LDG prefetch(kt+BK) ; MMA on buf s.
// ---------------------------------------------------------------------------
#define BM 128
#define BN 128
#define BK 32
#define A_PAD 36
#define B_PAD 136
#define GEMM_SMEM_BYTES ((2 * BM * A_PAD + 2 * BK * B_PAD) * sizeof(float))  // 71680

__global__ __launch_bounds__(256) void tf32_gemm_kernel(
    const float* __restrict__ A, const float* __restrict__ Bm,
    const float* __restrict__ bias, float* __restrict__ C,
    int M, int N, int K, int hasBias)
{
    extern __shared__ float gsm[];
    float* As = gsm;                      // [2][BM][A_PAD]
    float* Bs = gsm + 2 * BM * A_PAD;     // [2][BK][B_PAD]

    const int tid  = threadIdx.x;
    const int warp = tid >> 5;
    const int lane = tid & 31;
    const int g = lane >> 2;
    const int t = lane & 3;
    const int wm = (warp >> 2) * 64;
    const int wn = (warp & 3) * 32;
    const int m_blk = blockIdx.y * BM;
    const int n_blk = blockIdx.x * BN;

    const int a_r = tid >> 3;          // 0..31 (stride 32)
    const int a_c = (tid & 7) * 4;     // 0..28
    const int b_r = tid >> 5;          // 0..7  (stride 8)
    const int b_c = (tid & 31) * 4;    // 0..124

    const float* Ag = A + (size_t)(m_blk + a_r) * K + a_c;
    const float* Bg = Bm + (size_t)b_r * N + n_blk + b_c;

    float acc[4][4][4];
#pragma unroll
    for (int i = 0; i < 4; i++)
#pragma unroll
        for (int j = 0; j < 4; j++)
#pragma unroll
            for (int c = 0; c < 4; c++) acc[i][j][c] = 0.f;

    float4 pa[4], pb[4];
#pragma unroll
    for (int it = 0; it < 4; it++) {
        pa[it] = *(const float4*)(Ag + (size_t)(it * 32) * K);
        pb[it] = *(const float4*)(Bg + (size_t)(it * 8) * N);
    }

    int s = 0;
    for (int kt = 0; kt < K; kt += BK) {
        // store current stage (RNA tf32 rounding) into buffer s
#pragma unroll
        for (int it = 0; it < 4; it++) {
            float4 v = pa[it];
            float4 w;
            w.x = to_tf32(v.x); w.y = to_tf32(v.y);
            w.z = to_tf32(v.z); w.w = to_tf32(v.w);
            *(float4*)&As[(s * BM + a_r + it * 32) * A_PAD + a_c] = w;
            v = pb[it];
            w.x = to_tf32(v.x); w.y = to_tf32(v.y);
            w.z = to_tf32(v.z); w.w = to_tf32(v.w);
            *(float4*)&Bs[(s * BK + b_r + it * 8) * B_PAD + b_c] = w;
        }
        __syncthreads();

        // prefetch next stage into registers (overlaps the MMAs below)
        if (kt + BK < K) {
#pragma unroll
            for (int it = 0; it < 4; it++) {
                pa[it] = *(const float4*)(Ag + (kt + BK) + (size_t)(it * 32) * K);
                pb[it] = *(const float4*)(Bg + (size_t)(kt + BK + it * 8) * N);
            }
        }

#pragma unroll
        for (int kk = 0; kk < 4; kk++) {
            const int k0 = kk * 8;
            uint32_t af[4][4], bf[4][2];
#pragma unroll
            for (int i = 0; i < 4; i++) {
                const float* ab = &As[(s * BM + wm + i * 16 + g) * A_PAD + k0 + t];
                af[i][0] = __float_as_uint(ab[0]);
                af[i][1] = __float_as_uint(ab[8 * A_PAD]);
                af[i][2] = __float_as_uint(ab[4]);
                af[i][3] = __float_as_uint(ab[8 * A_PAD + 4]);
            }
#pragma unroll
            for (int j = 0; j < 4; j++) {
                const float* bb = &Bs[(s * BK + k0 + t) * B_PAD + wn + j * 8 + g];
                bf[j][0] = __float_as_uint(bb[0]);
                bf[j][1] = __float_as_uint(bb[4 * B_PAD]);
            }
#pragma unroll
            for (int i = 0; i < 4; i++)
#pragma unroll
                for (int j = 0; j < 4; j++)
                    mma_tf32(acc[i][j], af[i], bf[j]);
        }
        s ^= 1;
    }

#pragma unroll
    for (int i = 0; i < 4; i++) {
#pragma unroll
        for (int j = 0; j < 4; j++) {
            int row = m_blk + wm + i * 16 + g;
            int col = n_blk + wn + j * 8 + t * 2;
            float b0 = 0.f, b1 = 0.f;
            if (hasBias) { b0 = bias[col]; b1 = bias[col + 1]; }
            float2 v0 = make_float2(acc[i][j][0] + b0, acc[i][j][1] + b1);
            float2 v1 = make_float2(acc[i][j][2] + b0, acc[i][j][3] + b1);
            *(float2*)&C[(size_t)row * N + col] = v0;
            *(float2*)&C[(size_t)(row + 8) * N + col] = v1;
        }
    }
}

// ---------------------------------------------------------------------------
// GLM partial RoPE (unchanged)
// ---------------------------------------------------------------------------
__global__ void rope_kernel(float* __restrict__ qkv, const int* __restrict__ positions)
{
    int idx = blockIdx.x * blockDim.x + threadIdx.x;
    const int total = TOKS * (NH_ + NKV_) * (ROT_ / 2);
    if (idx >= total) return;
    int i = idx & 31;
    int head = (idx >> 5) % (NH_ + NKV_);
    int tok = idx / ((NH_ + NKV_) * 32);
    int pos = positions[tok];

    double freq = exp(-((double)(2 * i) / (double)ROT_) * log(10000.0));
    double ang = (double)pos * freq;
    float c = (float)cos(ang);
    float s = (float)sin(ang);

    int off = (head < NH_) ? head * HD_ : (NH_ * HD_ + (head - NH_) * HD_);
    float* p = qkv + (size_t)tok * QKV_N + off + 2 * i;
    float x1 = p[0], x2 = p[1];
    p[0] = x1 * c - x2 * s;
    p[1] = x1 * s + x2 * c;
}

// ---------------------------------------------------------------------------
// TF32 tensor-core causal GQA flash attention (unchanged from R11; bounds
// re-verified: Kn max idx 8443 < 8448, Vs max idx 8695 < 8704).
//   - K natural layout Kn[j][0..127], pad 132 (K-frag bank 4g+t, CF).
//   - V natural, pad 136 (V-frag bank 8t+g, CF).
//   - Q fragments loaded straight from gmem (one-time), no smem staging.
//   - Dynamic smem 68608 B.
// ---------------------------------------------------------------------------
#define AT_BM 128
#define AT_BN 64
#define KN_PAD 132
#define VN_PAD 136
#define AT_SMEM_BYTES ((AT_BN * KN_PAD + AT_BN * VN_PAD) * sizeof(float))

__global__ __launch_bounds__(256, 1) void attn_tc_kernel(
    const float* __restrict__ qkv, float* __restrict__ out)
{
    extern __shared__ float sm[];
    float* Kn = sm;                        // [64][KN_PAD]
    float* Vs = sm + AT_BN * KN_PAD;       // [64][VN_PAD]

    const int qt = blockIdx.x;            // q tile (128 rows)
    const int h  = blockIdx.y;
    const int b  = blockIdx.z;
    const int kvh = h >> 4;               // G = 16
    const int tid = threadIdx.x;
    const int lane = tid & 31;
    const int warp = tid >> 5;
    const int g = lane >> 2;
    const int t = lane & 3;

    const int r0 = warp * 16 + g;
    const int row0 = qt * AT_BM + r0;
    const int row1 = row0 + 8;

    const float* kbase = qkv + (size_t)b * S_ * QKV_N + NH_ * HD_ + kvh * HD_;
    const float* vbase = kbase + NKV_ * HD_;

    // ---- Q fragments directly from gmem (one-time) ----
    const float* q0 = qkv + (size_t)(b * S_ + row0) * QKV_N + h * HD_;
    const float* q1 = q0 + (size_t)8 * QKV_N;
    uint32_t qf[16][4];
#pragma unroll
    for (int kc = 0; kc < 16; kc++) {
        qf[kc][0] = __float_as_uint(to_tf32(q0[kc * 8 + t]));
        qf[kc][1] = __float_as_uint(to_tf32(q1[kc * 8 + t]));
        qf[kc][2] = __float_as_uint(to_tf32(q0[kc * 8 + t + 4]));
        qf[kc][3] = __float_as_uint(to_tf32(q1[kc * 8 + t + 4]));
    }

    float oacc[16][4];
#pragma unroll
    for (int nc = 0; nc < 16; nc++)
#pragma unroll
        for (int c = 0; c < 4; c++) oacc[nc][c] = 0.f;

    float m0 = -1e30f, m1 = -1e30f, l0 = 0.f, l1 = 0.f;
    const float scale = 0.08838834764831845f;   // 1/sqrt(128)

    const int n_tiles = 2 * qt + 2;

    const int lrow = tid >> 5;            // 0..7 (row base for loads)
    const int lc4  = (tid & 31) * 4;      // 0..124

    for (int kt = 0; kt < n_tiles; kt++) {
        const int kb = kt * AT_BN;
        __syncthreads();   // prior-iteration readers done before overwrite

        // ---- load K and V tiles, natural layout, coalesced STS.128 ----
#pragma unroll
        for (int it = 0; it < 8; it++) {
            int row = lrow + it * 8;
            size_t goff = (size_t)(kb + row) * QKV_N + lc4;
            float4 k4 = *(const float4*)(kbase + goff);
            float4 v4 = *(const float4*)(vbase + goff);
            float4 wk, wv;
            wk.x = to_tf32(k4.x); wk.y = to_tf32(k4.y);
            wk.z = to_tf32(k4.z); wk.w = to_tf32(k4.w);
            wv.x = to_tf32(v4.x); wv.y = to_tf32(v4.y);
            wv.z = to_tf32(v4.z); wv.w = to_tf32(v4.w);
            *(float4*)&Kn[row * KN_PAD + lc4] = wk;
            *(float4*)&Vs[row * VN_PAD + lc4] = wv;
        }
        __syncthreads();

        // ---- S = Q @ K^T : bf[jc] = K[jc*8+g][kc*8+t(+4)] ----
        float sacc[8][4];
#pragma unroll
        for (int jc = 0; jc < 8; jc++)
#pragma unroll
            for (int c = 0; c < 4; c++) sacc[jc][c] = 0.f;

#pragma unroll
        for (int kc = 0; kc < 16; kc++) {
            uint32_t bf[8][2];
#pragma unroll
            for (int jc = 0; jc < 8; jc++) {
                bf[jc][0] = __float_as_uint(Kn[(jc * 8 + g) * KN_PAD + kc * 8 + t]);
                bf[jc][1] = __float_as_uint(Kn[(jc * 8 + g) * KN_PAD + kc * 8 + t + 4]);
            }
#pragma unroll
            for (int jc = 0; jc < 8; jc++)
                mma_tf32(sacc[jc], qf[kc], bf[jc]);
        }

        // ---- scale + causal mask + online softmax ----
        const bool msk = (kt >= 2 * qt);
        float mx0 = -1e30f, mx1 = -1e30f;
#pragma unroll
        for (int jc = 0; jc < 8; jc++) {
            int c0 = kb + jc * 8 + 2 * t;
            int c1 = c0 + 1;
            float s0 = sacc[jc][0] * scale;
            float s1 = sacc[jc][1] * scale;
            float s2 = sacc[jc][2] * scale;
            float s3 = sacc[jc][3] * scale;
            if (msk) {
                if (c0 > row0) s0 = -1e30f;
                if (c1 > row0) s1 = -1e30f;
                if (c0 > row1) s2 = -1e30f;
                if (c1 > row1) s3 = -1e30f;
            }
            sacc[jc][0] = s0; sacc[jc][1] = s1;
            sacc[jc][2] = s2; sacc[jc][3] = s3;
            mx0 = fmaxf(mx0, fmaxf(s0, s1));
            mx1 = fmaxf(mx1, fmaxf(s2, s3));
        }
        mx0 = fmaxf(mx0, __shfl_xor_sync(0xffffffffu, mx0, 1));
        mx0 = fmaxf(mx0, __shfl_xor_sync(0xffffffffu, mx0, 2));
        mx1 = fmaxf(mx1, __shfl_xor_sync(0xffffffffu, mx1, 1));
        mx1 = fmaxf(mx1, __shfl_xor_sync(0xffffffffu, mx1, 2));

        float mn0 = fmaxf(m0, mx0), mn1 = fmaxf(m1, mx1);
        float al0 = __expf(m0 - mn0), al1 = __expf(m1 - mn1);
        m0 = mn0; m1 = mn1;

        float lt0 = 0.f, lt1 = 0.f;
#pragma unroll
        for (int jc = 0; jc < 8; jc++) {
            float p0 = __expf(sacc[jc][0] - mn0);
            float p1 = __expf(sacc[jc][1] - mn0);
            float p2 = __expf(sacc[jc][2] - mn1);
            float p3 = __expf(sacc[jc][3] - mn1);
            sacc[jc][0] = p0; sacc[jc][1] = p1;
            sacc[jc][2] = p2; sacc[jc][3] = p3;
            lt0 += p0 + p1;
            lt1 += p2 + p3;
        }
        lt0 += __shfl_xor_sync(0xffffffffu, lt0, 1);
        lt0 += __shfl_xor_sync(0xffffffffu, lt0, 2);
        lt1 += __shfl_xor_sync(0xffffffffu, lt1, 1);
        lt1 += __shfl_xor_sync(0xffffffffu, lt1, 2);
        l0 = l0 * al0 + lt0;
        l1 = l1 * al1 + lt1;

#pragma unroll
        for (int nc = 0; nc < 16; nc++) {
            oacc[nc][0] *= al0; oacc[nc][1] *= al0;
            oacc[nc][2] *= al1; oacc[nc][3] *= al1;
        }

        // ---- O += P @ V (P C-layout -> A-layout via quad shuffles) ----
        const int src0 = (lane & 28) | (t >> 1);
        const int src1 = src0 | 2;
        const bool odd = (t & 1);
#pragma unroll
        for (int jc = 0; jc < 8; jc++) {
            float p0 = to_tf32(sacc[jc][0]);
            float p1 = to_tf32(sacc[jc][1]);
            float p2 = to_tf32(sacc[jc][2]);
            float p3 = to_tf32(sacc[jc][3]);
            float x00 = __shfl_sync(0xffffffffu, p0, src0);
            float x10 = __shfl_sync(0xffffffffu, p1, src0);
            float x01 = __shfl_sync(0xffffffffu, p0, src1);
            float x11 = __shfl_sync(0xffffffffu, p1, src1);
            float x20 = __shfl_sync(0xffffffffu, p2, src0);
            float x30 = __shfl_sync(0xffffffffu, p3, src0);
            float x21 = __shfl_sync(0xffffffffu, p2, src1);
            float x31 = __shfl_sync(0xffffffffu, p3, src1);
            uint32_t a[4];
            a[0] = __float_as_uint(odd ? x10 : x00);   // (g,    t)
            a[1] = __float_as_uint(odd ? x30 : x20);   // (g+8,  t)
            a[2] = __float_as_uint(odd ? x11 : x01);   // (g,    t+4)
            a[3] = __float_as_uint(odd ? x31 : x21);   // (g+8,  t+4)
#pragma unroll
            for (int nc = 0; nc < 16; nc++) {
                uint32_t bv[2];
                bv[0] = __float_as_uint(Vs[(jc * 8 + t) * VN_PAD + nc * 8 + g]);
                bv[1] = __float_as_uint(Vs[(jc * 8 + t + 4) * VN_PAD + nc * 8 + g]);
                mma_tf32(oacc[nc], a, bv);
            }
        }
    }

    // ---- epilogue ----
    float il0 = 1.f / l0, il1 = 1.f / l1;
    float* o0 = out + (size_t)(b * S_ + row0) * H_ + h * HD_ + 2 * t;
    float* o1 = out + (size_t)(b * S_ + row1) * H_ + h * HD_ + 2 * t;
#pragma unroll
    for (int nc = 0; nc < 16; nc++) {
        *(float2*)(o0 + nc * 8) = make_float2(oacc[nc][0] * il0, oacc[nc][1] * il0);
        *(float2*)(o1 + nc * 8) = make_float2(oacc[nc][2] * il1, oacc[nc][3] * il1);
    }
}

// ---------------------------------------------------------------------------
extern "C" void kernel_launch(void* const* d_in, const int* in_sizes, int n_in,
                              void* d_out, int out_size)
{
    const float* hidden    = (const float*)d_in[0];
    const float* w_qkv     = (const float*)d_in[1];
    const float* b_qkv     = (const float*)d_in[2];
    const float* w_dense   = (const float*)d_in[3];
    const int*   positions = (const int*)d_in[4];
    float* out = (float*)d_out;

    float* qkv_buf = nullptr;
    float* attn_buf = nullptr;
    cudaGetSymbolAddress((void**)&qkv_buf, g_qkv);
    cudaGetSymbolAddress((void**)&attn_buf, g_attn);

    cudaFuncSetAttribute(tf32_gemm_kernel, cudaFuncAttributeMaxDynamicSharedMemorySize,
                         (int)GEMM_SMEM_BYTES);
    cudaFuncSetAttribute(attn_tc_kernel, cudaFuncAttributeMaxDynamicSharedMemorySize,
                         (int)AT_SMEM_BYTES);

    // 1) QKV GEMM + bias (tf32, double-buffered)
    tf32_gemm_kernel<<<dim3(QKV_N / BN, TOKS / BM), 256, GEMM_SMEM_BYTES>>>(
        hidden, w_qkv, b_qkv, qkv_buf, TOKS, QKV_N, H_, 1);

    // 2) RoPE in place on q + k heads
    {
        int total = TOKS * (NH_ + NKV_) * (ROT_ / 2);
        rope_kernel<<<(total + 255) / 256, 256>>>(qkv_buf, positions);
    }

    // 3) causal GQA flash attention (tf32 tensor cores)
    attn_tc_kernel<<<dim3(S_ / AT_BM, NH_, B_), 256, AT_SMEM_BYTES>>>(qkv_buf, attn_buf);

    // 4) dense GEMM (tf32, double-buffered)
    tf32_gemm_kernel<<<dim3(H_ / BN, TOKS / BM), 256, GEMM_SMEM_BYTES>>>(
        attn_buf, w_dense, nullptr, out, TOKS, H_, H_, 0);
}

// round 15
// speedup vs baseline: 1.0909x; 1.0909x over previous
#include <cuda_runtime.h>
#include <cuda_bf16.h>
#include <cstdint>
#include <math.h>

// Problem constants
#define B_   2
#define S_   2048
#define H_   4096
#define NH_  32
#define NKV_ 2
#define HD_  128
#define ROT_ 64
#define QKV_N 4608            // (NH + 2*NKV) * HD
#define TOKS (B_ * S_)        // 4096

// Scratch (device globals; no allocation allowed)
__device__ float g_qkv[(size_t)TOKS * QKV_N];   // ~75.5 MB
__device__ float g_attn[(size_t)TOKS * H_];     // ~67 MB

__device__ __forceinline__ float to_tf32(float x) {
    float y;
    asm("cvt.rna.tf32.f32 %0, %1;" : "=f"(y) : "f"(x));
    return y;
}

__device__ __forceinline__ void mma_tf32(float* d,
                                         const uint32_t* a,
                                         const uint32_t* b) {
    asm volatile(
        "mma.sync.aligned.m16n8k8.row.col.f32.tf32.tf32.f32 "
        "{%0,%1,%2,%3}, {%4,%5,%6,%7}, {%8,%9}, {%0,%1,%2,%3};\n"
        : "+f"(d[0]), "+f"(d[1]), "+f"(d[2]), "+f"(d[3])
        : "r"(a[0]), "r"(a[1]), "r"(a[2]), "r"(a[3]),
          "r"(b[0]), "r"(b[1]));
}

// ---------------------------------------------------------------------------
// TF32 tensor-core GEMM — exact R9 configuration (measured 868 us):
// single-buffered STATIC smem, 124 regs, 2 CTAs/SM. The R12 double-buffer
// variant regressed (164 regs -> 1 CTA/SM); reverted.
// ---------------------------------------------------------------------------
#define BM 128
#define BN 128
#define BK 32
#define A_PAD 36
#define B_PAD 136

__global__ __launch_bounds__(256) void tf32_gemm_kernel(
    const float* __restrict__ A, const float* __restrict__ Bm,
    const float* __restrict__ bias, float* __restrict__ C,
    int M, int N, int K, int hasBias)
{
    __shared__ float As[BM][A_PAD];
    __shared__ float Bs[BK][B_PAD];

    const int tid  = threadIdx.x;
    const int warp = tid >> 5;
    const int lane = tid & 31;
    const int g = lane >> 2;
    const int t = lane & 3;
    const int wm = (warp >> 2) * 64;
    const int wn = (warp & 3) * 32;
    const int m_blk = blockIdx.y * BM;
    const int n_blk = blockIdx.x * BN;

    const int a_r = tid >> 3;
    const int a_c = (tid & 7) * 4;
    const int b_r = tid >> 5;
    const int b_c = (tid & 31) * 4;

    const float* Ag = A + (size_t)(m_blk + a_r) * K + a_c;
    const float* Bg = Bm + (size_t)b_r * N + n_blk + b_c;

    float acc[4][4][4];
#pragma unroll
    for (int i = 0; i < 4; i++)
#pragma unroll
        for (int j = 0; j < 4; j++)
#pragma unroll
            for (int c = 0; c < 4; c++) acc[i][j][c] = 0.f;

    float4 pa[4], pb[4];
#pragma unroll
    for (int it = 0; it < 4; it++) {
        pa[it] = *(const float4*)(Ag + (size_t)(it * 32) * K);
        pb[it] = *(const float4*)(Bg + (size_t)(it * 8) * N);
    }

    for (int kt = 0; kt < K; kt += BK) {
#pragma unroll
        for (int it = 0; it < 4; it++) {
            float4 v = pa[it];
            float4 w;
            w.x = to_tf32(v.x); w.y = to_tf32(v.y);
            w.z = to_tf32(v.z); w.w = to_tf32(v.w);
            *(float4*)&As[a_r + it * 32][a_c] = w;
            v = pb[it];
            w.x = to_tf32(v.x); w.y = to_tf32(v.y);
            w.z = to_tf32(v.z); w.w = to_tf32(v.w);
            *(float4*)&Bs[b_r + it * 8][b_c] = w;
        }
        __syncthreads();

        if (kt + BK < K) {
#pragma unroll
            for (int it = 0; it < 4; it++) {
                pa[it] = *(const float4*)(Ag + (kt + BK) + (size_t)(it * 32) * K);
                pb[it] = *(const float4*)(Bg + (size_t)(kt + BK + it * 8) * N);
            }
        }

#pragma unroll
        for (int kk = 0; kk < 4; kk++) {
            const int k0 = kk * 8;
            uint32_t af[4][4], bf[4][2];
#pragma unroll
            for (int i = 0; i < 4; i++) {
                const float* ab = &As[wm + i * 16 + g][k0 + t];
                af[i][0] = __float_as_uint(ab[0]);
                af[i][1] = __float_as_uint(ab[8 * A_PAD]);
                af[i][2] = __float_as_uint(ab[4]);
                af[i][3] = __float_as_uint(ab[8 * A_PAD + 4]);
            }
#pragma unroll
            for (int j = 0; j < 4; j++) {
                const float* bb = &Bs[k0 + t][wn + j * 8 + g];
                bf[j][0] = __float_as_uint(bb[0]);
                bf[j][1] = __float_as_uint(bb[4 * B_PAD]);
            }
#pragma unroll
            for (int i = 0; i < 4; i++)
#pragma unroll
                for (int j = 0; j < 4; j++)
                    mma_tf32(acc[i][j], af[i], bf[j]);
        }
        __syncthreads();
    }

#pragma unroll
    for (int i = 0; i < 4; i++) {
#pragma unroll
        for (int j = 0; j < 4; j++) {
            int row = m_blk + wm + i * 16 + g;
            int col = n_blk + wn + j * 8 + t * 2;
            float b0 = 0.f, b1 = 0.f;
            if (hasBias) { b0 = bias[col]; b1 = bias[col + 1]; }
            float2 v0 = make_float2(acc[i][j][0] + b0, acc[i][j][1] + b1);
            float2 v1 = make_float2(acc[i][j][2] + b0, acc[i][j][3] + b1);
            *(float2*)&C[(size_t)row * N + col] = v0;
            *(float2*)&C[(size_t)(row + 8) * N + col] = v1;
        }
    }
}

// ---------------------------------------------------------------------------
// GLM partial RoPE (unchanged)
// ---------------------------------------------------------------------------
__global__ void rope_kernel(float* __restrict__ qkv, const int* __restrict__ positions)
{
    int idx = blockIdx.x * blockDim.x + threadIdx.x;
    const int total = TOKS * (NH_ + NKV_) * (ROT_ / 2);
    if (idx >= total) return;
    int i = idx & 31;
    int head = (idx >> 5) % (NH_ + NKV_);
    int tok = idx / ((NH_ + NKV_) * 32);
    int pos = positions[tok];

    double freq = exp(-((double)(2 * i) / (double)ROT_) * log(10000.0));
    double ang = (double)pos * freq;
    float c = (float)cos(ang);
    float s = (float)sin(ang);

    int off = (head < NH_) ? head * HD_ : (NH_ * HD_ + (head - NH_) * HD_);
    float* p = qkv + (size_t)tok * QKV_N + off + 2 * i;
    float x1 = p[0], x2 = p[1];
    p[0] = x1 * c - x2 * s;
    p[1] = x1 * s + x2 * c;
}

// ---------------------------------------------------------------------------
// TF32 tensor-core causal GQA flash attention (R12 version, measured good).
//   - K natural layout Kn[j][0..127], pad 132 (K-frag bank 4g+t, CF).
//   - V natural, pad 136 (V-frag bank 8t+g, CF).
//   - Q fragments loaded straight from gmem (one-time), no smem staging.
//   - Dynamic smem 68608 B.
// ---------------------------------------------------------------------------
#define AT_BM 128
#define AT_BN 64
#define KN_PAD 132
#define VN_PAD 136
#define AT_SMEM_BYTES ((AT_BN * KN_PAD + AT_BN * VN_PAD) * sizeof(float))

__global__ __launch_bounds__(256, 1) void attn_tc_kernel(
    const float* __restrict__ qkv, float* __restrict__ out)
{
    extern __shared__ float sm[];
    float* Kn = sm;                        // [64][KN_PAD]
    float* Vs = sm + AT_BN * KN_PAD;       // [64][VN_PAD]

    const int qt = blockIdx.x;            // q tile (128 rows)
    const int h  = blockIdx.y;
    const int b  = blockIdx.z;
    const int kvh = h >> 4;               // G = 16
    const int tid = threadIdx.x;
    const int lane = tid & 31;
    const int warp = tid >> 5;
    const int g = lane >> 2;
    const int t = lane & 3;

    const int r0 = warp * 16 + g;
    const int row0 = qt * AT_BM + r0;
    const int row1 = row0 + 8;

    const float* kbase = qkv + (size_t)b * S_ * QKV_N + NH_ * HD_ + kvh * HD_;
    const float* vbase = kbase + NKV_ * HD_;

    // ---- Q fragments directly from gmem (one-time) ----
    const float* q0 = qkv + (size_t)(b * S_ + row0) * QKV_N + h * HD_;
    const float* q1 = q0 + (size_t)8 * QKV_N;
    uint32_t qf[16][4];
#pragma unroll
    for (int kc = 0; kc < 16; kc++) {
        qf[kc][0] = __float_as_uint(to_tf32(q0[kc * 8 + t]));
        qf[kc][1] = __float_as_uint(to_tf32(q1[kc * 8 + t]));
        qf[kc][2] = __float_as_uint(to_tf32(q0[kc * 8 + t + 4]));
        qf[kc][3] = __float_as_uint(to_tf32(q1[kc * 8 + t + 4]));
    }

    float oacc[16][4];
#pragma unroll
    for (int nc = 0; nc < 16; nc++)
#pragma unroll
        for (int c = 0; c < 4; c++) oacc[nc][c] = 0.f;

    float m0 = -1e30f, m1 = -1e30f, l0 = 0.f, l1 = 0.f;
    const float scale = 0.08838834764831845f;   // 1/sqrt(128)

    const int n_tiles = 2 * qt + 2;

    const int lrow = tid >> 5;            // 0..7 (row base for loads)
    const int lc4  = (tid & 31) * 4;      // 0..124

    for (int kt = 0; kt < n_tiles; kt++) {
        const int kb = kt * AT_BN;
        __syncthreads();   // prior-iteration readers done before overwrite

        // ---- load K and V tiles, natural layout, coalesced STS.128 ----
#pragma unroll
        for (int it = 0; it < 8; it++) {
            int row = lrow + it * 8;
            size_t goff = (size_t)(kb + row) * QKV_N + lc4;
            float4 k4 = *(const float4*)(kbase + goff);
            float4 v4 = *(const float4*)(vbase + goff);
            float4 wk, wv;
            wk.x = to_tf32(k4.x); wk.y = to_tf32(k4.y);
            wk.z = to_tf32(k4.z); wk.w = to_tf32(k4.w);
            wv.x = to_tf32(v4.x); wv.y = to_tf32(v4.y);
            wv.z = to_tf32(v4.z); wv.w = to_tf32(v4.w);
            *(float4*)&Kn[row * KN_PAD + lc4] = wk;
            *(float4*)&Vs[row * VN_PAD + lc4] = wv;
        }
        __syncthreads();

        // ---- S = Q @ K^T : bf[jc] = K[jc*8+g][kc*8+t(+4)] ----
        float sacc[8][4];
#pragma unroll
        for (int jc = 0; jc < 8; jc++)
#pragma unroll
            for (int c = 0; c < 4; c++) sacc[jc][c] = 0.f;

#pragma unroll
        for (int kc = 0; kc < 16; kc++) {
            uint32_t bf[8][2];
#pragma unroll
            for (int jc = 0; jc < 8; jc++) {
                bf[jc][0] = __float_as_uint(Kn[(jc * 8 + g) * KN_PAD + kc * 8 + t]);
                bf[jc][1] = __float_as_uint(Kn[(jc * 8 + g) * KN_PAD + kc * 8 + t + 4]);
            }
#pragma unroll
            for (int jc = 0; jc < 8; jc++)
                mma_tf32(sacc[jc], qf[kc], bf[jc]);
        }

        // ---- scale + causal mask + online softmax ----
        const bool msk = (kt >= 2 * qt);
        float mx0 = -1e30f, mx1 = -1e30f;
#pragma unroll
        for (int jc = 0; jc < 8; jc++) {
            int c0 = kb + jc * 8 + 2 * t;
            int c1 = c0 + 1;
            float s0 = sacc[jc][0] * scale;
            float s1 = sacc[jc][1] * scale;
            float s2 = sacc[jc][2] * scale;
            float s3 = sacc[jc][3] * scale;
            if (msk) {
                if (c0 > row0) s0 = -1e30f;
                if (c1 > row0) s1 = -1e30f;
                if (c0 > row1) s2 = -1e30f;
                if (c1 > row1) s3 = -1e30f;
            }
            sacc[jc][0] = s0; sacc[jc][1] = s1;
            sacc[jc][2] = s2; sacc[jc][3] = s3;
            mx0 = fmaxf(mx0, fmaxf(s0, s1));
            mx1 = fmaxf(mx1, fmaxf(s2, s3));
        }
        mx0 = fmaxf(mx0, __shfl_xor_sync(0xffffffffu, mx0, 1));
        mx0 = fmaxf(mx0, __shfl_xor_sync(0xffffffffu, mx0, 2));
        mx1 = fmaxf(mx1, __shfl_xor_sync(0xffffffffu, mx1, 1));
        mx1 = fmaxf(mx1, __shfl_xor_sync(0xffffffffu, mx1, 2));

        float mn0 = fmaxf(m0, mx0), mn1 = fmaxf(m1, mx1);
        float al0 = __expf(m0 - mn0), al1 = __expf(m1 - mn1);
        m0 = mn0; m1 = mn1;

        float lt0 = 0.f, lt1 = 0.f;
#pragma unroll
        for (int jc = 0; jc < 8; jc++) {
            float p0 = __expf(sacc[jc][0] - mn0);
            float p1 = __expf(sacc[jc][1] - mn0);
            float p2 = __expf(sacc[jc][2] - mn1);
            float p3 = __expf(sacc[jc][3] - mn1);
            sacc[jc][0] = p0; sacc[jc][1] = p1;
            sacc[jc][2] = p2; sacc[jc][3] = p3;
            lt0 += p0 + p1;
            lt1 += p2 + p3;
        }
        lt0 += __shfl_xor_sync(0xffffffffu, lt0, 1);
        lt0 += __shfl_xor_sync(0xffffffffu, lt0, 2);
        lt1 += __shfl_xor_sync(0xffffffffu, lt1, 1);
        lt1 += __shfl_xor_sync(0xffffffffu, lt1, 2);
        l0 = l0 * al0 + lt0;
        l1 = l1 * al1 + lt1;

#pragma unroll
        for (int nc = 0; nc < 16; nc++) {
            oacc[nc][0] *= al0; oacc[nc][1] *= al0;
            oacc[nc][2] *= al1; oacc[nc][3] *= al1;
        }

        // ---- O += P @ V (P C-layout -> A-layout via quad shuffles) ----
        const int src0 = (lane & 28) | (t >> 1);
        const int src1 = src0 | 2;
        const bool odd = (t & 1);
#pragma unroll
        for (int jc = 0; jc < 8; jc++) {
            float p0 = to_tf32(sacc[jc][0]);
            float p1 = to_tf32(sacc[jc][1]);
            float p2 = to_tf32(sacc[jc][2]);
            float p3 = to_tf32(sacc[jc][3]);
            float x00 = __shfl_sync(0xffffffffu, p0, src0);
            float x10 = __shfl_sync(0xffffffffu, p1, src0);
            float x01 = __shfl_sync(0xffffffffu, p0, src1);
            float x11 = __shfl_sync(0xffffffffu, p1, src1);
            float x20 = __shfl_sync(0xffffffffu, p2, src0);
            float x30 = __shfl_sync(0xffffffffu, p3, src0);
            float x21 = __shfl_sync(0xffffffffu, p2, src1);
            float x31 = __shfl_sync(0xffffffffu, p3, src1);
            uint32_t a[4];
            a[0] = __float_as_uint(odd ? x10 : x00);   // (g,    t)
            a[1] = __float_as_uint(odd ? x30 : x20);   // (g+8,  t)
            a[2] = __float_as_uint(odd ? x11 : x01);   // (g,    t+4)
            a[3] = __float_as_uint(odd ? x31 : x21);   // (g+8,  t+4)
#pragma unroll
            for (int nc = 0; nc < 16; nc++) {
                uint32_t bv[2];
                bv[0] = __float_as_uint(Vs[(jc * 8 + t) * VN_PAD + nc * 8 + g]);
                bv[1] = __float_as_uint(Vs[(jc * 8 + t + 4) * VN_PAD + nc * 8 + g]);
                mma_tf32(oacc[nc], a, bv);
            }
        }
    }

    // ---- epilogue ----
    float il0 = 1.f / l0, il1 = 1.f / l1;
    float* o0 = out + (size_t)(b * S_ + row0) * H_ + h * HD_ + 2 * t;
    float* o1 = out + (size_t)(b * S_ + row1) * H_ + h * HD_ + 2 * t;
#pragma unroll
    for (int nc = 0; nc < 16; nc++) {
        *(float2*)(o0 + nc * 8) = make_float2(oacc[nc][0] * il0, oacc[nc][1] * il0);
        *(float2*)(o1 + nc * 8) = make_float2(oacc[nc][2] * il1, oacc[nc][3] * il1);
    }
}

// ---------------------------------------------------------------------------
extern "C" void kernel_launch(void* const* d_in, const int* in_sizes, int n_in,
                              void* d_out, int out_size)
{
    const float* hidden    = (const float*)d_in[0];
    const float* w_qkv     = (const float*)d_in[1];
    const float* b_qkv     = (const float*)d_in[2];
    const float* w_dense   = (const float*)d_in[3];
    const int*   positions = (const int*)d_in[4];
    float* out = (float*)d_out;

    float* qkv_buf = nullptr;
    float* attn_buf = nullptr;
    cudaGetSymbolAddress((void**)&qkv_buf, g_qkv);
    cudaGetSymbolAddress((void**)&attn_buf, g_attn);

    cudaFuncSetAttribute(attn_tc_kernel, cudaFuncAttributeMaxDynamicSharedMemorySize,
                         (int)AT_SMEM_BYTES);

    // 1) QKV GEMM + bias (tf32, single-buffer R9 config)
    tf32_gemm_kernel<<<dim3(QKV_N / BN, TOKS / BM), 256>>>(
        hidden, w_qkv, b_qkv, qkv_buf, TOKS, QKV_N, H_, 1);

    // 2) RoPE in place on q + k heads
    {
        int total = TOKS * (NH_ + NKV_) * (ROT_ / 2);
        rope_kernel<<<(total + 255) / 256, 256>>>(qkv_buf, positions);
    }

    // 3) causal GQA flash attention (tf32 tensor cores)
    attn_tc_kernel<<<dim3(S_ / AT_BM, NH_, B_), 256, AT_SMEM_BYTES>>>(qkv_buf, attn_buf);

    // 4) dense GEMM (tf32, single-buffer R9 config)
    tf32_gemm_kernel<<<dim3(H_ / BN, TOKS / BM), 256>>>(
        attn_buf, w_dense, nullptr, out, TOKS, H_, H_, 0);
}

// round 17
// speedup vs baseline: 1.1772x; 1.0791x over previous
#include <cuda_runtime.h>
#include <cuda_bf16.h>
#include <cstdint>
#include <math.h>

// Problem constants
#define B_   2
#define S_   2048
#define H_   4096
#define NH_  32
#define NKV_ 2
#define HD_  128
#define ROT_ 64
#define QKV_N 4608            // (NH + 2*NKV) * HD
#define TOKS (B_ * S_)        // 4096

// Scratch (device globals; no allocation allowed)
__device__ float g_qkv[(size_t)TOKS * QKV_N];   // ~75.5 MB
__device__ float g_attn[(size_t)TOKS * H_];     // rounded-hidden (ph.1) / attn out
__device__ float g_wt[(size_t)QKV_N * H_];      // rounded w_qkv (ph.1) / w_dense (ph.2)

__device__ __forceinline__ float to_tf32(float x) {
    float y;
    asm("cvt.rna.tf32.f32 %0, %1;" : "=f"(y) : "f"(x));
    return y;
}

__device__ __forceinline__ void mma_tf32(float* d,
                                         const uint32_t* a,
                                         const uint32_t* b) {
    asm volatile(
        "mma.sync.aligned.m16n8k8.row.col.f32.tf32.tf32.f32 "
        "{%0,%1,%2,%3}, {%4,%5,%6,%7}, {%8,%9}, {%0,%1,%2,%3};\n"
        : "+f"(d[0]), "+f"(d[1]), "+f"(d[2]), "+f"(d[3])
        : "r"(a[0]), "r"(a[1]), "r"(a[2]), "r"(a[3]),
          "r"(b[0]), "r"(b[1]));
}

__device__ __forceinline__ uint32_t smem_u32(const void* p) {
    uint32_t a;
    asm("{ .reg .u64 t; cvta.to.shared.u64 t, %1; cvt.u32.u64 %0, t; }" : "=r"(a) : "l"(p));
    return a;
}

#define CP_ASYNC16(dst_u32, src_ptr) \
    asm volatile("cp.async.cg.shared.global [%0], [%1], 16;" \
        :: "r"(dst_u32), "l"(src_ptr) : "memory")
#define CP_COMMIT() asm volatile("cp.async.commit_group;" ::: "memory")
#define CP_WAIT1()  asm volatile("cp.async.wait_group 1;" ::: "memory")
#define CP_WAIT0()  asm volatile("cp.async.wait_group 0;" ::: "memory")

// ---------------------------------------------------------------------------
// Pre-pass: elementwise RNA tf32 rounding
// ---------------------------------------------------------------------------
__global__ void round_tf32_kernel(const float4* __restrict__ src,
                                  float4* __restrict__ dst, int n4)
{
    int i = blockIdx.x * blockDim.x + threadIdx.x;
    if (i >= n4) return;
    float4 v = src[i];
    v.x = to_tf32(v.x); v.y = to_tf32(v.y);
    v.z = to_tf32(v.z); v.w = to_tf32(v.w);
    dst[i] = v;
}

// ---------------------------------------------------------------------------
// TF32 mma.sync GEMM with cp.async double buffer. Operands PRE-ROUNDED.
// C[M,N] = A[M,K] @ B[K,N] (+bias, optional output rounding).
// 128x128x32 CTA tile, 8 warps (2x4), warp tile 64x32 (R15 fragment scheme).
// Smem (dynamic, 71680 B): As[2][128][36], Bs[2][32][136]. 2 CTAs/SM forced.
// Pipeline per stage: issue cp.async(s+1) ; wait(s) ; sync ; mma(s) ; sync.
// ---------------------------------------------------------------------------
#define BM 128
#define BN 128
#define BK 32
#define A_PAD 36
#define B_PAD 136
#define GEMM_SMEM_BYTES ((2 * BM * A_PAD + 2 * BK * B_PAD) * sizeof(float))  // 71680

__global__ __launch_bounds__(256, 2) void tf32_gemm_ca_kernel(
    const float* __restrict__ A, const float* __restrict__ Bm,
    const float* __restrict__ bias, float* __restrict__ C,
    int M, int N, int K, int hasBias, int roundOut)
{
    extern __shared__ float gsm[];
    float* As = gsm;                        // [2][BM][A_PAD]
    float* Bs = gsm + 2 * BM * A_PAD;       // [2][BK][B_PAD]
    const uint32_t sA = smem_u32(As);
    const uint32_t sB = smem_u32(Bs);

    const int tid  = threadIdx.x;
    const int warp = tid >> 5;
    const int lane = tid & 31;
    const int g = lane >> 2;
    const int t = lane & 3;
    const int wm = (warp >> 2) * 64;
    const int wn = (warp & 3) * 32;
    const int m_blk = blockIdx.y * BM;
    const int n_blk = blockIdx.x * BN;

    const int a_r = tid >> 3;          // 0..31 (stride 32)
    const int a_c = (tid & 7) * 4;     // 0..28
    const int b_r = tid >> 5;          // 0..7  (stride 8)
    const int b_c = (tid & 31) * 4;    // 0..124

    const float* Ag = A + (size_t)(m_blk + a_r) * K + a_c;
    const float* Bg = Bm + (size_t)b_r * N + n_blk + b_c;

    float acc[4][4][4];
#pragma unroll
    for (int i = 0; i < 4; i++)
#pragma unroll
        for (int j = 0; j < 4; j++)
#pragma unroll
            for (int c = 0; c < 4; c++) acc[i][j][c] = 0.f;

    const int NST = K / BK;

    // issue stage s into buffer s&1 (8 cp.async / thread)
    auto issue = [&](int s) {
        const int p = s & 1;
        const int k0 = s * BK;
#pragma unroll
        for (int it = 0; it < 4; it++) {
            uint32_t da = sA + 4u * (uint32_t)((p * BM + a_r + it * 32) * A_PAD + a_c);
            CP_ASYNC16(da, Ag + k0 + (size_t)(it * 32) * K);
            uint32_t db = sB + 4u * (uint32_t)((p * BK + b_r + it * 8) * B_PAD + b_c);
            CP_ASYNC16(db, Bg + (size_t)(k0 + it * 8) * N);
        }
    };

    issue(0);
    CP_COMMIT();

    for (int s = 0; s < NST; s++) {
        const int p = s & 1;
        if (s + 1 < NST) { issue(s + 1); CP_COMMIT(); CP_WAIT1(); }
        else             { CP_WAIT0(); }
        __syncthreads();

#pragma unroll
        for (int kk = 0; kk < 4; kk++) {
            const int k0 = kk * 8;
            uint32_t af[4][4], bf[4][2];
#pragma unroll
            for (int i = 0; i < 4; i++) {
                const float* ab = &As[(p * BM + wm + i * 16 + g) * A_PAD + k0 + t];
                af[i][0] = __float_as_uint(ab[0]);
                af[i][1] = __float_as_uint(ab[8 * A_PAD]);
                af[i][2] = __float_as_uint(ab[4]);
                af[i][3] = __float_as_uint(ab[8 * A_PAD + 4]);
            }
#pragma unroll
            for (int j = 0; j < 4; j++) {
                const float* bb = &Bs[(p * BK + k0 + t) * B_PAD + wn + j * 8 + g];
                bf[j][0] = __float_as_uint(bb[0]);
                bf[j][1] = __float_as_uint(bb[4 * B_PAD]);
            }
#pragma unroll
            for (int i = 0; i < 4; i++)
#pragma unroll
                for (int j = 0; j < 4; j++)
                    mma_tf32(acc[i][j], af[i], bf[j]);
        }
        __syncthreads();   // before next iteration's issue overwrites buffer p
    }

#pragma unroll
    for (int i = 0; i < 4; i++) {
#pragma unroll
        for (int j = 0; j < 4; j++) {
            int row = m_blk + wm + i * 16 + g;
            int col = n_blk + wn + j * 8 + t * 2;
            float b0 = 0.f, b1 = 0.f;
            if (hasBias) { b0 = bias[col]; b1 = bias[col + 1]; }
            float2 v0 = make_float2(acc[i][j][0] + b0, acc[i][j][1] + b1);
            float2 v1 = make_float2(acc[i][j][2] + b0, acc[i][j][3] + b1);
            if (roundOut) {
                v0.x = to_tf32(v0.x); v0.y = to_tf32(v0.y);
                v1.x = to_tf32(v1.x); v1.y = to_tf32(v1.y);
            }
            *(float2*)&C[(size_t)row * N + col] = v0;
            *(float2*)&C[(size_t)(row + 8) * N + col] = v1;
        }
    }
}

// ---------------------------------------------------------------------------
// GLM partial RoPE — now RNA-rounds its outputs (inputs pre-rounded; the
// rotation products must be re-rounded so attention can consume raw).
// ---------------------------------------------------------------------------
__global__ void rope_kernel(float* __restrict__ qkv, const int* __restrict__ positions)
{
    int idx = blockIdx.x * blockDim.x + threadIdx.x;
    const int total = TOKS * (NH_ + NKV_) * (ROT_ / 2);
    if (idx >= total) return;
    int i = idx & 31;
    int head = (idx >> 5) % (NH_ + NKV_);
    int tok = idx / ((NH_ + NKV_) * 32);
    int pos = positions[tok];

    double freq = exp(-((double)(2 * i) / (double)ROT_) * log(10000.0));
    double ang = (double)pos * freq;
    float c = (float)cos(ang);
    float s = (float)sin(ang);

    int off = (head < NH_) ? head * HD_ : (NH_ * HD_ + (head - NH_) * HD_);
    float* p = qkv + (size_t)tok * QKV_N + off + 2 * i;
    float x1 = p[0], x2 = p[1];
    p[0] = to_tf32(x1 * c - x2 * s);
    p[1] = to_tf32(x1 * s + x2 * c);
}

// ---------------------------------------------------------------------------
// TF32 mma.sync causal GQA flash attention, cp.async double-buffered K/V.
// Inputs pre-rounded (GEMM1 epilogue + RoPE) -> loaders are raw copies.
// Epilogue RNA-rounds output (pre-rounds dense GEMM's A operand).
// Smem: Kn[2][64][132] + Vs[2][64][136] = 137216 B dynamic. qt reversed (LPT).
// ---------------------------------------------------------------------------
#define AT_BM 128
#define AT_BN 64
#define KN_PAD 132
#define VN_PAD 136
#define AT_STAGE_FLOATS (AT_BN * KN_PAD + AT_BN * VN_PAD)   // 17152
#define AT_SMEM_BYTES (2 * AT_STAGE_FLOATS * sizeof(float)) // 137216

__global__ __launch_bounds__(256, 1) void attn_tc_kernel(
    const float* __restrict__ qkv, float* __restrict__ out)
{
    extern __shared__ float sm[];
    // buffer p: Kn at sm + p*AT_STAGE_FLOATS, Vs right after Kn
    const uint32_t sbase = smem_u32(sm);

    const int qt = (int)gridDim.x - 1 - (int)blockIdx.x;   // heavy tiles first
    const int h  = blockIdx.y;
    const int b  = blockIdx.z;
    const int kvh = h >> 4;               // G = 16
    const int tid = threadIdx.x;
    const int lane = tid & 31;
    const int warp = tid >> 5;
    const int g = lane >> 2;
    const int t = lane & 3;

    const int r0 = warp * 16 + g;
    const int row0 = qt * AT_BM + r0;
    const int row1 = row0 + 8;

    const float* kbase = qkv + (size_t)b * S_ * QKV_N + NH_ * HD_ + kvh * HD_;
    const float* vbase = kbase + NKV_ * HD_;

    // ---- Q fragments directly from gmem (pre-rounded; no cvt) ----
    const float* q0 = qkv + (size_t)(b * S_ + row0) * QKV_N + h * HD_;
    const float* q1 = q0 + (size_t)8 * QKV_N;
    uint32_t qf[16][4];
#pragma unroll
    for (int kc = 0; kc < 16; kc++) {
        qf[kc][0] = __float_as_uint(q0[kc * 8 + t]);
        qf[kc][1] = __float_as_uint(q1[kc * 8 + t]);
        qf[kc][2] = __float_as_uint(q0[kc * 8 + t + 4]);
        qf[kc][3] = __float_as_uint(q1[kc * 8 + t + 4]);
    }

    float oacc[16][4];
#pragma unroll
    for (int nc = 0; nc < 16; nc++)
#pragma unroll
        for (int c = 0; c < 4; c++) oacc[nc][c] = 0.f;

    float m0 = -1e30f, m1 = -1e30f, l0 = 0.f, l1 = 0.f;
    const float scale = 0.08838834764831845f;   // 1/sqrt(128)

    const int n_tiles = 2 * qt + 2;
    const int lrow = tid >> 5;            // 0..7
    const int lc4  = (tid & 31) * 4;      // 0..124

    auto issue = [&](int kt) {
        const int p = kt & 1;
        const int kb = kt * AT_BN;
        const uint32_t kbuf = sbase + 4u * (uint32_t)(p * AT_STAGE_FLOATS);
        const uint32_t vbuf = kbuf + 4u * (uint32_t)(AT_BN * KN_PAD);
#pragma unroll
        for (int it = 0; it < 8; it++) {
            int row = lrow + it * 8;
            size_t goff = (size_t)(kb + row) * QKV_N + lc4;
            CP_ASYNC16(kbuf + 4u * (uint32_t)(row * KN_PAD + lc4), kbase + goff);
            CP_ASYNC16(vbuf + 4u * (uint32_t)(row * VN_PAD + lc4), vbase + goff);
        }
    };

    issue(0);
    CP_COMMIT();

    for (int kt = 0; kt < n_tiles; kt++) {
        const int p = kt & 1;
        const int kb = kt * AT_BN;
        if (kt + 1 < n_tiles) { issue(kt + 1); CP_COMMIT(); CP_WAIT1(); }
        else                  { CP_WAIT0(); }
        __syncthreads();

        const float* Kn = sm + p * AT_STAGE_FLOATS;
        const float* Vs = Kn + AT_BN * KN_PAD;

        // ---- S = Q @ K^T ----
        float sacc[8][4];
#pragma unroll
        for (int jc = 0; jc < 8; jc++)
#pragma unroll
            for (int c = 0; c < 4; c++) sacc[jc][c] = 0.f;

#pragma unroll
        for (int kc = 0; kc < 16; kc++) {
            uint32_t bf[8][2];
#pragma unroll
            for (int jc = 0; jc < 8; jc++) {
                bf[jc][0] = __float_as_uint(Kn[(jc * 8 + g) * KN_PAD + kc * 8 + t]);
                bf[jc][1] = __float_as_uint(Kn[(jc * 8 + g) * KN_PAD + kc * 8 + t + 4]);
            }
#pragma unroll
            for (int jc = 0; jc < 8; jc++)
                mma_tf32(sacc[jc], qf[kc], bf[jc]);
        }

        // ---- scale + causal mask + online softmax ----
        const bool msk = (kt >= 2 * qt);
        float mx0 = -1e30f, mx1 = -1e30f;
#pragma unroll
        for (int jc = 0; jc < 8; jc++) {
            int c0 = kb + jc * 8 + 2 * t;
            int c1 = c0 + 1;
            float s0 = sacc[jc][0] * scale;
            float s1 = sacc[jc][1] * scale;
            float s2 = sacc[jc][2] * scale;
            float s3 = sacc[jc][3] * scale;
            if (msk) {
                if (c0 > row0) s0 = -1e30f;
                if (c1 > row0) s1 = -1e30f;
                if (c0 > row1) s2 = -1e30f;
                if (c1 > row1) s3 = -1e30f;
            }
            sacc[jc][0] = s0; sacc[jc][1] = s1;
            sacc[jc][2] = s2; sacc[jc][3] = s3;
            mx0 = fmaxf(mx0, fmaxf(s0, s1));
            mx1 = fmaxf(mx1, fmaxf(s2, s3));
        }
        mx0 = fmaxf(mx0, __shfl_xor_sync(0xffffffffu, mx0, 1));
        mx0 = fmaxf(mx0, __shfl_xor_sync(0xffffffffu, mx0, 2));
        mx1 = fmaxf(mx1, __shfl_xor_sync(0xffffffffu, mx1, 1));
        mx1 = fmaxf(mx1, __shfl_xor_sync(0xffffffffu, mx1, 2));

        float mn0 = fmaxf(m0, mx0), mn1 = fmaxf(m1, mx1);
        float al0 = __expf(m0 - mn0), al1 = __expf(m1 - mn1);
        m0 = mn0; m1 = mn1;

        float lt0 = 0.f, lt1 = 0.f;
#pragma unroll
        for (int jc = 0; jc < 8; jc++) {
            float p0 = __expf(sacc[jc][0] - mn0);
            float p1 = __expf(sacc[jc][1] - mn0);
            float p2 = __expf(sacc[jc][2] - mn1);
            float p3 = __expf(sacc[jc][3] - mn1);
            sacc[jc][0] = p0; sacc[jc][1] = p1;
            sacc[jc][2] = p2; sacc[jc][3] = p3;
            lt0 += p0 + p1;
            lt1 += p2 + p3;
        }
        lt0 += __shfl_xor_sync(0xffffffffu, lt0, 1);
        lt0 += __shfl_xor_sync(0xffffffffu, lt0, 2);
        lt1 += __shfl_xor_sync(0xffffffffu, lt1, 1);
        lt1 += __shfl_xor_sync(0xffffffffu, lt1, 2);
        l0 = l0 * al0 + lt0;
        l1 = l1 * al1 + lt1;

#pragma unroll
        for (int nc = 0; nc < 16; nc++) {
            oacc[nc][0] *= al0; oacc[nc][1] *= al0;
            oacc[nc][2] *= al1; oacc[nc][3] *= al1;
        }

        // ---- O += P @ V (P C-layout -> A-layout via quad shuffles) ----
        const int src0 = (lane & 28) | (t >> 1);
        const int src1 = src0 | 2;
        const bool odd = (t & 1);
#pragma unroll
        for (int jc = 0; jc < 8; jc++) {
            float p0 = to_tf32(sacc[jc][0]);
            float p1 = to_tf32(sacc[jc][1]);
            float p2 = to_tf32(sacc[jc][2]);
            float p3 = to_tf32(sacc[jc][3]);
            float x00 = __shfl_sync(0xffffffffu, p0, src0);
            float x10 = __shfl_sync(0xffffffffu, p1, src0);
            float x01 = __shfl_sync(0xffffffffu, p0, src1);
            float x11 = __shfl_sync(0xffffffffu, p1, src1);
            float x20 = __shfl_sync(0xffffffffu, p2, src0);
            float x30 = __shfl_sync(0xffffffffu, p3, src0);
            float x21 = __shfl_sync(0xffffffffu, p2, src1);
            float x31 = __shfl_sync(0xffffffffu, p3, src1);
            uint32_t a[4];
            a[0] = __float_as_uint(odd ? x10 : x00);
            a[1] = __float_as_uint(odd ? x30 : x20);
            a[2] = __float_as_uint(odd ? x11 : x01);
            a[3] = __float_as_uint(odd ? x31 : x21);
#pragma unroll
            for (int nc = 0; nc < 16; nc++) {
                uint32_t bv[2];
                bv[0] = __float_as_uint(Vs[(jc * 8 + t) * VN_PAD + nc * 8 + g]);
                bv[1] = __float_as_uint(Vs[(jc * 8 + t + 4) * VN_PAD + nc * 8 + g]);
                mma_tf32(oacc[nc], a, bv);
            }
        }
        __syncthreads();   // before next iteration's issue overwrites buffer p
    }

    // epilogue: normalize + RNA-round (pre-rounds dense GEMM's A operand)
    float il0 = 1.f / l0, il1 = 1.f / l1;
    float* o0 = out + (size_t)(b * S_ + row0) * H_ + h * HD_ + 2 * t;
    float* o1 = out + (size_t)(b * S_ + row1) * H_ + h * HD_ + 2 * t;
#pragma unroll
    for (int nc = 0; nc < 16; nc++) {
        *(float2*)(o0 + nc * 8) = make_float2(to_tf32(oacc[nc][0] * il0),
                                             to_tf32(oacc[nc][1] * il0));
        *(float2*)(o1 + nc * 8) = make_float2(to_tf32(oacc[nc][2] * il1),
                                             to_tf32(oacc[nc][3] * il1));
    }
}

// ---------------------------------------------------------------------------
extern "C" void kernel_launch(void* const* d_in, const int* in_sizes, int n_in,
                              void* d_out, int out_size)
{
    const float* hidden    = (const float*)d_in[0];
    const float* w_qkv     = (const float*)d_in[1];
    const float* b_qkv     = (const float*)d_in[2];
    const float* w_dense   = (const float*)d_in[3];
    const int*   positions = (const int*)d_in[4];
    float* out = (float*)d_out;

    float* qkv_buf = nullptr;
    float* attn_buf = nullptr;
    float* wt_buf = nullptr;
    cudaGetSymbolAddress((void**)&qkv_buf, g_qkv);
    cudaGetSymbolAddress((void**)&attn_buf, g_attn);
    cudaGetSymbolAddress((void**)&wt_buf, g_wt);

    cudaFuncSetAttribute(tf32_gemm_ca_kernel, cudaFuncAttributeMaxDynamicSharedMemorySize,
                         (int)GEMM_SMEM_BYTES);
    cudaFuncSetAttribute(attn_tc_kernel, cudaFuncAttributeMaxDynamicSharedMemorySize,
                         (int)AT_SMEM_BYTES);

    // 0a) round hidden -> attn_buf (A of GEMM1)
    {
        int n4 = TOKS * H_ / 4;
        round_tf32_kernel<<<(n4 + 255) / 256, 256>>>(
            (const float4*)hidden, (float4*)attn_buf, n4);
    }
    // 0b) round w_qkv -> wt_buf (B of GEMM1, natural [K][N] layout)
    {
        int n4 = H_ * QKV_N / 4;
        round_tf32_kernel<<<(n4 + 255) / 256, 256>>>(
            (const float4*)w_qkv, (float4*)wt_buf, n4);
    }

    // 1) QKV GEMM + bias (cp.async tf32); output rounded for attention
    tf32_gemm_ca_kernel<<<dim3(QKV_N / BN, TOKS / BM), 256, GEMM_SMEM_BYTES>>>(
        attn_buf, wt_buf, b_qkv, qkv_buf, TOKS, QKV_N, H_, 1, 1);

    // 1b) round w_dense -> wt_buf (stream-ordered after GEMM1 consumed it)
    {
        int n4 = H_ * H_ / 4;
        round_tf32_kernel<<<(n4 + 255) / 256, 256>>>(
            (const float4*)w_dense, (float4*)wt_buf, n4);
    }

    // 2) RoPE in place (re-rounds rotated values)
    {
        int total = TOKS * (NH_ + NKV_) * (ROT_ / 2);
        rope_kernel<<<(total + 255) / 256, 256>>>(qkv_buf, positions);
    }

    // 3) causal GQA flash attention (cp.async); output rounded for GEMM2
    attn_tc_kernel<<<dim3(S_ / AT_BM, NH_, B_), 256, AT_SMEM_BYTES>>>(qkv_buf, attn_buf);

    // 4) dense GEMM (cp.async tf32); final output NOT rounded
    tf32_gemm_ca_kernel<<<dim3(H_ / BN, TOKS / BM), 256, GEMM_SMEM_BYTES>>>(
        attn_buf, wt_buf, nullptr, out, TOKS, H_, H_, 0, 0);
}